// round 11
// baseline (speedup 1.0000x reference)
#include <cuda_runtime.h>
#include <cuda_fp16.h>

#define NN 200000
#define EE 3200000

// ---- device scratch (no runtime allocation allowed) ----
__device__ int      g_is64;
__device__ int      g_cnt_src[NN];
__device__ int      g_cnt_dst[NN];
__device__ int      g_fill[NN];
__device__ int      g_rowptr[NN];
__device__ float    g_dinv[NN];
__device__ unsigned g_cursor;
__device__ int2     g_pairs[EE];       // (src, w-bits) grouped contiguously by dst
__device__ float4   g_h [NN * 8];      // 32 floats per node, float4-viewed
__device__ float4   g_a [NN * 8];
__device__ float4   g_t1[NN * 8];
__device__ uint2    g_xh [NN * 8];     // fp16 shadow of current conv input (gather source)
__device__ uint2    g_t1h[NN * 8];     // fp16 shadow of T1 (gather source)

// ---------------------------------------------------------------- helpers

__device__ __forceinline__ uint2 pack_h4(float4 v) {
    __half2 lo = __floats2half2_rn(v.x, v.y);
    __half2 hi = __floats2half2_rn(v.z, v.w);
    uint2 r;
    r.x = *reinterpret_cast<unsigned*>(&lo);
    r.y = *reinterpret_cast<unsigned*>(&hi);
    return r;
}

// ---------------------------------------------------------------- dtype detect

// Genuine int64 indices are all < NN; int32 data reinterpreted as int64 gives
// huge values almost surely. Sampled slots stay inside the buffer under either
// dtype (int32 buffer = 3.2M int64 slots; max sample 62812).
__global__ void k_detect(const void* __restrict__ eiraw) {
    const long long* p = (const long long*)eiraw;
    int ok = 1;
    for (int i = 0; i < 64; i++) {
        long long v = p[i * 997 + 1];
        if (v < 0 || v >= NN) { ok = 0; break; }
    }
    g_is64 = ok;
}

__device__ __forceinline__ void decode_edge(const void* eiraw, int e, int& s, int& d) {
    if (g_is64) {
        const long long* p = (const long long*)eiraw;
        s = (int)p[e];
        d = (int)p[EE + e];
    } else {
        const int* p = (const int*)eiraw;
        s = p[e];
        d = p[EE + e];
    }
}

// ---------------------------------------------------------------- CSR build

__global__ void k_zero() {
    int i = blockIdx.x * 256 + threadIdx.x;
    if (i < NN) { g_cnt_src[i] = 0; g_cnt_dst[i] = 0; g_fill[i] = 0; }
    if (i == 0) g_cursor = 0u;
}

__global__ void k_count(const void* __restrict__ eiraw) {
    int e = blockIdx.x * 256 + threadIdx.x;
    if (e >= EE) return;
    int s, d;
    decode_edge(eiraw, e, s, d);
    if ((unsigned)s >= NN || (unsigned)d >= NN) return;
    atomicAdd(&g_cnt_src[s], 1);
    atomicAdd(&g_cnt_dst[d], 1);
}

// dinv + contiguous row allocation (placement order irrelevant)
__global__ void k_dinv_rowalloc() {
    int i = blockIdx.x * 256 + threadIdx.x;
    if (i >= NN) return;
    int c = g_cnt_src[i];
    g_dinv[i] = (c > 0) ? rsqrtf((float)c) : 0.0f;
    g_rowptr[i] = (int)atomicAdd(&g_cursor, (unsigned)g_cnt_dst[i]);
}

__global__ void k_fill(const void* __restrict__ eiraw) {
    int e = blockIdx.x * 256 + threadIdx.x;
    if (e >= EE) return;
    int s, d;
    decode_edge(eiraw, e, s, d);
    if ((unsigned)s >= NN || (unsigned)d >= NN) return;
    float w = -g_dinv[s] * g_dinv[d];
    int pos = g_rowptr[d] + atomicAdd(&g_fill[d], 1);
    g_pairs[pos] = make_int2(s, __float_as_int(w));
}

// ---------------------------------------------------------------- input layer

// h = relu(x @ W0 + b0). 8 lanes per node, lane handles 4 output features.
__global__ void __launch_bounds__(256) k_input(const float* __restrict__ x,
                                               const float* __restrict__ W0,
                                               const float* __restrict__ b0) {
    int tid = blockIdx.x * 256 + threadIdx.x;
    int n = tid >> 3, c = tid & 7;
    if (n >= NN) return;
    float x0 = __ldg(&x[n * 3 + 0]);
    float x1 = __ldg(&x[n * 3 + 1]);
    float x2 = __ldg(&x[n * 3 + 2]);
    const float4* W04 = (const float4*)W0;
    float4 w0 = __ldg(&W04[c]);
    float4 w1 = __ldg(&W04[8 + c]);
    float4 w2 = __ldg(&W04[16 + c]);
    float4 acc = __ldg(&((const float4*)b0)[c]);
    acc.x = fmaf(x0, w0.x, fmaf(x1, w1.x, fmaf(x2, w2.x, acc.x)));
    acc.y = fmaf(x0, w0.y, fmaf(x1, w1.y, fmaf(x2, w2.y, acc.y)));
    acc.z = fmaf(x0, w0.z, fmaf(x1, w1.z, fmaf(x2, w2.z, acc.z)));
    acc.w = fmaf(x0, w0.w, fmaf(x1, w1.w, fmaf(x2, w2.w, acc.w)));
    acc.x = fmaxf(acc.x, 0.0f); acc.y = fmaxf(acc.y, 0.0f);
    acc.z = fmaxf(acc.z, 0.0f); acc.w = fmaxf(acc.w, 0.0f);
    g_h[n * 8 + c] = acc;
    g_xh[n * 8 + c] = pack_h4(acc);
}

// ---------------------------------------------------------------- propagation

// Row accumulation gathering from the fp16 shadow: 8 lanes per node, lane
// loads 8B (4 features) -> 64B per node row, fp32 accumulation.
__device__ __forceinline__ float4 prop_row4h(const uint2* __restrict__ Xh,
                                             int row, int deg, int c) {
    float4 acc = make_float4(0.f, 0.f, 0.f, 0.f);
#pragma unroll 8
    for (int k = 0; k < deg; k++) {
        int2 pr = __ldg(&g_pairs[row + k]);     // uniform within 8-lane group
        float w  = __int_as_float(pr.y);
        uint2 u  = __ldg(&Xh[pr.x * 8 + c]);    // 8B per lane, 64B per row
        __half2 h0 = *reinterpret_cast<__half2*>(&u.x);
        __half2 h1 = *reinterpret_cast<__half2*>(&u.y);
        float2 f0 = __half22float2(h0);
        float2 f1 = __half22float2(h1);
        acc.x = fmaf(w, f0.x, acc.x);
        acc.y = fmaf(w, f0.y, acc.y);
        acc.z = fmaf(w, f1.x, acc.z);
        acc.w = fmaf(w, f1.y, acc.w);
    }
    return acc;
}

// T1 = L~ X  (gathers Xh shadow), writes fp32 T1 + fp16 shadow T1h
__global__ void __launch_bounds__(256, 6) k_prop_csr(float4* __restrict__ Y) {
    int tid = blockIdx.x * 256 + threadIdx.x;
    int n = tid >> 3, c = tid & 7;
    if (n >= NN) return;
    int row = __ldg(&g_rowptr[n]);
    int deg = __ldg(&g_cnt_dst[n]);
    float4 y = prop_row4h(g_xh, row, deg, c);
    Y[n * 8 + c] = y;
    g_t1h[n * 8 + c] = pack_h4(y);
}

__device__ __forceinline__ float getc(const float4& v, int comp) {
    return comp == 0 ? v.x : comp == 1 ? v.y : comp == 2 ? v.z : v.w;
}

// Second propagation fused with combine:
// y = L~ T1 (gathers T1h) ; T2 = 2y - X ; out = X@W[0]+T1@W[1]+T2@W[2]+b [+res][relu]
// Writes fp32 out + fp16 shadow (next conv's gather source).
__global__ void __launch_bounds__(256, 4) k_prop_combine(const float4* __restrict__ X,
                                                         const float4* __restrict__ T1,
                                                         const float* __restrict__ W,
                                                         const float* __restrict__ bias,
                                                         const float4* __restrict__ res,
                                                         float4* __restrict__ out,
                                                         int doRelu) {
    __shared__ float4 sW[768];   // [3][32][8] float4 view of W[3][32][32]
    __shared__ float4 sB[8];
    for (int i = threadIdx.x; i < 768; i += 256) sW[i] = ((const float4*)W)[i];
    if (threadIdx.x < 8) sB[threadIdx.x] = ((const float4*)bias)[threadIdx.x];
    __syncthreads();

    int tid = blockIdx.x * 256 + threadIdx.x;
    int n = tid >> 3, c = tid & 7;
    if (n >= NN) return;
    int row = __ldg(&g_rowptr[n]);
    int deg = __ldg(&g_cnt_dst[n]);

    float4 xv  = __ldg(&X[n * 8 + c]);     // issue row reads before gather loop
    float4 t1v = __ldg(&T1[n * 8 + c]);
    float4 y   = prop_row4h(g_t1h, row, deg, c);
    float4 t2v = make_float4(2.0f * y.x - xv.x, 2.0f * y.y - xv.y,
                             2.0f * y.z - xv.z, 2.0f * y.w - xv.w);

    float4 acc = sB[c];
    if (res) {
        float4 rr = __ldg(&res[n * 8 + c]);
        acc.x += rr.x; acc.y += rr.y; acc.z += rr.z; acc.w += rr.w;
    }
#pragma unroll
    for (int i = 0; i < 32; i++) {
        const int src = i >> 2, comp = i & 3;           // compile-time
        float xi = __shfl_sync(0xffffffffu, getc(xv,  comp), src, 8);
        float ai = __shfl_sync(0xffffffffu, getc(t1v, comp), src, 8);
        float ti = __shfl_sync(0xffffffffu, getc(t2v, comp), src, 8);
        float4 wx = sW[i * 8 + c];
        float4 wa = sW[256 + i * 8 + c];
        float4 wt = sW[512 + i * 8 + c];
        acc.x = fmaf(xi, wx.x, fmaf(ai, wa.x, fmaf(ti, wt.x, acc.x)));
        acc.y = fmaf(xi, wx.y, fmaf(ai, wa.y, fmaf(ti, wt.y, acc.y)));
        acc.z = fmaf(xi, wx.z, fmaf(ai, wa.z, fmaf(ti, wt.z, acc.z)));
        acc.w = fmaf(xi, wx.w, fmaf(ai, wa.w, fmaf(ti, wt.w, acc.w)));
    }
    if (doRelu) {
        acc.x = fmaxf(acc.x, 0.0f); acc.y = fmaxf(acc.y, 0.0f);
        acc.z = fmaxf(acc.z, 0.0f); acc.w = fmaxf(acc.w, 0.0f);
    }
    out[n * 8 + c] = acc;
    g_xh[n * 8 + c] = pack_h4(acc);   // gather source for next conv
}

// ---------------------------------------------------------------- output head

__global__ void __launch_bounds__(256) k_final(const float4* __restrict__ H,
                                               const float* __restrict__ W1,
                                               const float* __restrict__ b1,
                                               float* __restrict__ out) {
    int tid = blockIdx.x * 256 + threadIdx.x;
    int n = tid >> 3, c = tid & 7;
    if (n >= NN) return;
    float4 h = __ldg(&H[n * 8 + c]);
    float4 w = __ldg(&((const float4*)W1)[c]);
    float v = h.x * w.x + h.y * w.y + h.z * w.z + h.w * w.w;
    v += __shfl_down_sync(0xffffffffu, v, 4, 8);
    v += __shfl_down_sync(0xffffffffu, v, 2, 8);
    v += __shfl_down_sync(0xffffffffu, v, 1, 8);
    if (c == 0) out[n] = v + __ldg(b1);
}

// ---------------------------------------------------------------- launch

extern "C" void kernel_launch(void* const* d_in, const int* in_sizes, int n_in,
                              void* d_out, int out_size) {
    // ---- resolve inputs by element count (robust to metadata ordering) ----
    int idx_x = 0, idx_ei = 1, idx_W0 = 2, idx_b1 = 13;
    int chebW[4] = {4, 6, 8, 10};
    int chebB[4] = {5, 7, 9, 11};
    int idx_b0 = 3, idx_W1 = 12;
    {
        int cw[4], ncw = 0, s32[8], ns = 0;
        int ix = -1, iei = -1, iw0 = -1, ib1 = -1;
        for (int i = 0; i < n_in; i++) {
            int s = in_sizes[i];
            if (s == 600000) ix = i;
            else if (s == 6400000) iei = i;
            else if (s == 96) iw0 = i;
            else if (s == 1) ib1 = i;
            else if (s == 3072 && ncw < 4) cw[ncw++] = i;
            else if (s == 32 && ns < 8) s32[ns++] = i;
        }
        if (ix >= 0 && iei >= 0 && iw0 >= 0 && ib1 >= 0 && ncw == 4 && ns == 6) {
            idx_x = ix; idx_ei = iei; idx_W0 = iw0; idx_b1 = ib1;
            int rem[2], nr = 0;
            for (int k = 0; k < 4; k++) chebW[k] = cw[k];
            for (int i = 0; i < 6; i++) {
                int isb = 0;
                for (int k = 0; k < 4; k++)
                    if (s32[i] == cw[k] + 1) { chebB[k] = s32[i]; isb = 1; }
                if (!isb && nr < 2) rem[nr++] = s32[i];
            }
            if (nr == 2) {
                if (rem[1] == rem[0] + 1) { idx_W1 = rem[0]; idx_b0 = rem[1]; }
                else                      { idx_b0 = rem[0]; idx_W1 = rem[1]; }
            }
        }
    }

    const float* x    = (const float*)d_in[idx_x];
    const void*  ei   = d_in[idx_ei];
    const float* W0   = (const float*)d_in[idx_W0];
    const float* b0   = (const float*)d_in[idx_b0];
    const float* cW[4], *cB[4];
    for (int k = 0; k < 4; k++) { cW[k] = (const float*)d_in[chebW[k]]; cB[k] = (const float*)d_in[chebB[k]]; }
    const float* W1   = (const float*)d_in[idx_W1];
    const float* b1   = (const float*)d_in[idx_b1];
    float*       out  = (float*)d_out;

    float4 *ph, *pa, *pt1;
    cudaGetSymbolAddress((void**)&ph,  g_h);
    cudaGetSymbolAddress((void**)&pa,  g_a);
    cudaGetSymbolAddress((void**)&pt1, g_t1);

    const int NB_N = (NN + 255) / 256;
    const int NB_E = (EE + 255) / 256;
    const int NB_8 = (NN * 8) / 256;     // 6250 blocks: 8 threads per node

    k_detect<<<1, 1>>>(ei);
    k_zero<<<NB_N, 256>>>();
    k_count<<<NB_E, 256>>>(ei);
    k_dinv_rowalloc<<<NB_N, 256>>>();
    k_fill<<<NB_E, 256>>>(ei);
    k_input<<<NB_8, 256>>>(x, W0, b0);

    auto cheb = [&](int k, const float4* Xb, const float4* resb, float4* outb) {
        k_prop_csr<<<NB_8, 256>>>(pt1);
        k_prop_combine<<<NB_8, 256>>>(Xb, pt1, cW[k], cB[k], resb, outb, 1);
    };

    // block 1: h0=h; h=relu(conv11(h)); h=relu(conv12(h)+h0)
    cheb(0, ph, nullptr, pa);
    cheb(1, pa, ph,      ph);
    // block 2
    cheb(2, ph, nullptr, pa);
    cheb(3, pa, ph,      ph);

    k_final<<<NB_8, 256>>>(ph, W1, b1, out);
}

// round 12
// speedup vs baseline: 1.0640x; 1.0640x over previous
#include <cuda_runtime.h>
#include <cuda_fp16.h>

#define NN 200000
#define EE 3200000

// ---- device scratch (no runtime allocation allowed) ----
__device__ int      g_is64;
__device__ int      g_cnt_src[NN];
__device__ int      g_cnt_dst[NN];
__device__ int      g_fill[NN];
__device__ int      g_rowptr[NN];
__device__ float    g_dinv[NN];
__device__ unsigned g_cursor;
__device__ int2     g_pairs[EE];       // (src, w-bits) grouped contiguously by dst
__device__ float4   g_h [NN * 8];      // 32 floats per node, float4-viewed
__device__ float4   g_a [NN * 8];
__device__ float4   g_t1[NN * 8];
__device__ uint4    g_xh [NN * 4];     // fp16 shadow of current conv input (gather source)
__device__ uint4    g_t1h[NN * 4];     // fp16 shadow of T1 (gather source)

// ---------------------------------------------------------------- helpers

__device__ __forceinline__ uint4 pack_h8(float4 a, float4 b) {
    __half2 p0 = __floats2half2_rn(a.x, a.y);
    __half2 p1 = __floats2half2_rn(a.z, a.w);
    __half2 p2 = __floats2half2_rn(b.x, b.y);
    __half2 p3 = __floats2half2_rn(b.z, b.w);
    uint4 r;
    r.x = *reinterpret_cast<unsigned*>(&p0);
    r.y = *reinterpret_cast<unsigned*>(&p1);
    r.z = *reinterpret_cast<unsigned*>(&p2);
    r.w = *reinterpret_cast<unsigned*>(&p3);
    return r;
}

// ---------------------------------------------------------------- dtype detect

// Genuine int64 indices are all < NN; int32 data reinterpreted as int64 gives
// huge values almost surely. Sampled slots stay inside the buffer under either
// dtype (int32 buffer = 3.2M int64 slots; max sample 62812).
__global__ void k_detect(const void* __restrict__ eiraw) {
    const long long* p = (const long long*)eiraw;
    int ok = 1;
    for (int i = 0; i < 64; i++) {
        long long v = p[i * 997 + 1];
        if (v < 0 || v >= NN) { ok = 0; break; }
    }
    g_is64 = ok;
}

__device__ __forceinline__ void decode_edge(const void* eiraw, int e, int& s, int& d) {
    if (g_is64) {
        const long long* p = (const long long*)eiraw;
        s = (int)p[e];
        d = (int)p[EE + e];
    } else {
        const int* p = (const int*)eiraw;
        s = p[e];
        d = p[EE + e];
    }
}

// ---------------------------------------------------------------- CSR build

__global__ void k_zero() {
    int i = blockIdx.x * 256 + threadIdx.x;
    if (i < NN) { g_cnt_src[i] = 0; g_cnt_dst[i] = 0; g_fill[i] = 0; }
    if (i == 0) g_cursor = 0u;
}

__global__ void k_count(const void* __restrict__ eiraw) {
    int e = blockIdx.x * 256 + threadIdx.x;
    if (e >= EE) return;
    int s, d;
    decode_edge(eiraw, e, s, d);
    if ((unsigned)s >= NN || (unsigned)d >= NN) return;
    atomicAdd(&g_cnt_src[s], 1);
    atomicAdd(&g_cnt_dst[d], 1);
}

// dinv + contiguous row allocation (placement order irrelevant)
__global__ void k_dinv_rowalloc() {
    int i = blockIdx.x * 256 + threadIdx.x;
    if (i >= NN) return;
    int c = g_cnt_src[i];
    g_dinv[i] = (c > 0) ? rsqrtf((float)c) : 0.0f;
    g_rowptr[i] = (int)atomicAdd(&g_cursor, (unsigned)g_cnt_dst[i]);
}

__global__ void k_fill(const void* __restrict__ eiraw) {
    int e = blockIdx.x * 256 + threadIdx.x;
    if (e >= EE) return;
    int s, d;
    decode_edge(eiraw, e, s, d);
    if ((unsigned)s >= NN || (unsigned)d >= NN) return;
    float w = -g_dinv[s] * g_dinv[d];
    int pos = g_rowptr[d] + atomicAdd(&g_fill[d], 1);
    g_pairs[pos] = make_int2(s, __float_as_int(w));
}

// ---------------------------------------------------------------- input layer

// h = relu(x @ W0 + b0). 4 lanes per node, lane handles 8 output features.
__global__ void __launch_bounds__(256) k_input(const float* __restrict__ x,
                                               const float* __restrict__ W0,
                                               const float* __restrict__ b0) {
    int tid = blockIdx.x * 256 + threadIdx.x;
    int n = tid >> 2, c = tid & 3;
    if (n >= NN) return;
    int c2 = c * 2;
    float x0 = __ldg(&x[n * 3 + 0]);
    float x1 = __ldg(&x[n * 3 + 1]);
    float x2 = __ldg(&x[n * 3 + 2]);
    const float4* W04 = (const float4*)W0;
    float4 a0 = __ldg(&((const float4*)b0)[c2]);
    float4 a1 = __ldg(&((const float4*)b0)[c2 + 1]);
#pragma unroll
    for (int r = 0; r < 3; r++) {
        float xr = r == 0 ? x0 : r == 1 ? x1 : x2;
        float4 w0 = __ldg(&W04[r * 8 + c2]);
        float4 w1 = __ldg(&W04[r * 8 + c2 + 1]);
        a0.x = fmaf(xr, w0.x, a0.x); a0.y = fmaf(xr, w0.y, a0.y);
        a0.z = fmaf(xr, w0.z, a0.z); a0.w = fmaf(xr, w0.w, a0.w);
        a1.x = fmaf(xr, w1.x, a1.x); a1.y = fmaf(xr, w1.y, a1.y);
        a1.z = fmaf(xr, w1.z, a1.z); a1.w = fmaf(xr, w1.w, a1.w);
    }
    a0.x = fmaxf(a0.x, 0.f); a0.y = fmaxf(a0.y, 0.f);
    a0.z = fmaxf(a0.z, 0.f); a0.w = fmaxf(a0.w, 0.f);
    a1.x = fmaxf(a1.x, 0.f); a1.y = fmaxf(a1.y, 0.f);
    a1.z = fmaxf(a1.z, 0.f); a1.w = fmaxf(a1.w, 0.f);
    g_h[n * 8 + c2]     = a0;
    g_h[n * 8 + c2 + 1] = a1;
    g_xh[n * 4 + c] = pack_h8(a0, a1);
}

// ---------------------------------------------------------------- propagation

// Row accumulation from the fp16 shadow: 4 lanes per node, lane loads 16B
// (8 features); a warp covers 8 nodes -> 8 edges per warp gather-LDG.
__device__ __forceinline__ void prop_row8h(const uint4* __restrict__ Xh,
                                           int row, int deg, int c,
                                           float4& a0, float4& a1) {
    a0 = make_float4(0.f, 0.f, 0.f, 0.f);
    a1 = make_float4(0.f, 0.f, 0.f, 0.f);
#pragma unroll 8
    for (int k = 0; k < deg; k++) {
        int2 pr = __ldg(&g_pairs[row + k]);     // uniform within 4-lane group
        float w  = __int_as_float(pr.y);
        uint4 u  = __ldg(&Xh[pr.x * 4 + c]);    // 16B per lane, 64B per row
        float2 f0 = __half22float2(*reinterpret_cast<__half2*>(&u.x));
        float2 f1 = __half22float2(*reinterpret_cast<__half2*>(&u.y));
        float2 f2 = __half22float2(*reinterpret_cast<__half2*>(&u.z));
        float2 f3 = __half22float2(*reinterpret_cast<__half2*>(&u.w));
        a0.x = fmaf(w, f0.x, a0.x); a0.y = fmaf(w, f0.y, a0.y);
        a0.z = fmaf(w, f1.x, a0.z); a0.w = fmaf(w, f1.y, a0.w);
        a1.x = fmaf(w, f2.x, a1.x); a1.y = fmaf(w, f2.y, a1.y);
        a1.z = fmaf(w, f3.x, a1.z); a1.w = fmaf(w, f3.y, a1.w);
    }
}

// T1 = L~ X  (gathers Xh shadow), writes fp32 T1 + fp16 shadow T1h
__global__ void __launch_bounds__(256) k_prop_csr(float4* __restrict__ Y) {
    int tid = blockIdx.x * 256 + threadIdx.x;
    int n = tid >> 2, c = tid & 3;
    if (n >= NN) return;
    int row = __ldg(&g_rowptr[n]);
    int deg = __ldg(&g_cnt_dst[n]);
    float4 a0, a1;
    prop_row8h(g_xh, row, deg, c, a0, a1);
    Y[n * 8 + c * 2]     = a0;
    Y[n * 8 + c * 2 + 1] = a1;
    g_t1h[n * 4 + c] = pack_h8(a0, a1);
}

__device__ __forceinline__ float getc8(const float4& a, const float4& b, int comp) {
    switch (comp) {
        case 0: return a.x; case 1: return a.y; case 2: return a.z; case 3: return a.w;
        case 4: return b.x; case 5: return b.y; case 6: return b.z; default: return b.w;
    }
}

// Second propagation fused with combine:
// y = L~ T1 (gathers T1h) ; T2 = 2y - X ; out = X@W[0]+T1@W[1]+T2@W[2]+b [+res][relu]
// Width-4 shfl broadcasts serve all 8 node-groups of the warp at once.
__global__ void __launch_bounds__(256) k_prop_combine(const float4* __restrict__ X,
                                                      const float4* __restrict__ T1,
                                                      const float* __restrict__ W,
                                                      const float* __restrict__ bias,
                                                      const float4* __restrict__ res,
                                                      float4* __restrict__ out,
                                                      int doRelu) {
    __shared__ float4 sW[768];   // [3][32][8] float4 view of W[3][32][32]
    __shared__ float4 sB[8];
    for (int i = threadIdx.x; i < 768; i += 256) sW[i] = ((const float4*)W)[i];
    if (threadIdx.x < 8) sB[threadIdx.x] = ((const float4*)bias)[threadIdx.x];
    __syncthreads();

    int tid = blockIdx.x * 256 + threadIdx.x;
    int n = tid >> 2, c = tid & 3;
    if (n >= NN) return;
    int c2 = c * 2;
    int row = __ldg(&g_rowptr[n]);
    int deg = __ldg(&g_cnt_dst[n]);

    float4 xv0  = __ldg(&X[n * 8 + c2]);
    float4 xv1  = __ldg(&X[n * 8 + c2 + 1]);
    float4 t1v0 = __ldg(&T1[n * 8 + c2]);
    float4 t1v1 = __ldg(&T1[n * 8 + c2 + 1]);
    float4 y0, y1;
    prop_row8h(g_t1h, row, deg, c, y0, y1);
    float4 t2v0 = make_float4(2.f * y0.x - xv0.x, 2.f * y0.y - xv0.y,
                              2.f * y0.z - xv0.z, 2.f * y0.w - xv0.w);
    float4 t2v1 = make_float4(2.f * y1.x - xv1.x, 2.f * y1.y - xv1.y,
                              2.f * y1.z - xv1.z, 2.f * y1.w - xv1.w);

    float4 a0 = sB[c2], a1 = sB[c2 + 1];
    if (res) {
        float4 r0 = __ldg(&res[n * 8 + c2]);
        float4 r1 = __ldg(&res[n * 8 + c2 + 1]);
        a0.x += r0.x; a0.y += r0.y; a0.z += r0.z; a0.w += r0.w;
        a1.x += r1.x; a1.y += r1.y; a1.z += r1.z; a1.w += r1.w;
    }
#pragma unroll
    for (int i = 0; i < 32; i++) {
        const int src = i >> 3, comp = i & 7;           // compile-time
        float xi = __shfl_sync(0xffffffffu, getc8(xv0,  xv1,  comp), src, 4);
        float ai = __shfl_sync(0xffffffffu, getc8(t1v0, t1v1, comp), src, 4);
        float ti = __shfl_sync(0xffffffffu, getc8(t2v0, t2v1, comp), src, 4);
        float4 wx0 = sW[i * 8 + c2],       wx1 = sW[i * 8 + c2 + 1];
        float4 wa0 = sW[256 + i * 8 + c2], wa1 = sW[256 + i * 8 + c2 + 1];
        float4 wt0 = sW[512 + i * 8 + c2], wt1 = sW[512 + i * 8 + c2 + 1];
        a0.x = fmaf(xi, wx0.x, fmaf(ai, wa0.x, fmaf(ti, wt0.x, a0.x)));
        a0.y = fmaf(xi, wx0.y, fmaf(ai, wa0.y, fmaf(ti, wt0.y, a0.y)));
        a0.z = fmaf(xi, wx0.z, fmaf(ai, wa0.z, fmaf(ti, wt0.z, a0.z)));
        a0.w = fmaf(xi, wx0.w, fmaf(ai, wa0.w, fmaf(ti, wt0.w, a0.w)));
        a1.x = fmaf(xi, wx1.x, fmaf(ai, wa1.x, fmaf(ti, wt1.x, a1.x)));
        a1.y = fmaf(xi, wx1.y, fmaf(ai, wa1.y, fmaf(ti, wt1.y, a1.y)));
        a1.z = fmaf(xi, wx1.z, fmaf(ai, wa1.z, fmaf(ti, wt1.z, a1.z)));
        a1.w = fmaf(xi, wx1.w, fmaf(ai, wa1.w, fmaf(ti, wt1.w, a1.w)));
    }
    if (doRelu) {
        a0.x = fmaxf(a0.x, 0.f); a0.y = fmaxf(a0.y, 0.f);
        a0.z = fmaxf(a0.z, 0.f); a0.w = fmaxf(a0.w, 0.f);
        a1.x = fmaxf(a1.x, 0.f); a1.y = fmaxf(a1.y, 0.f);
        a1.z = fmaxf(a1.z, 0.f); a1.w = fmaxf(a1.w, 0.f);
    }
    out[n * 8 + c2]     = a0;
    out[n * 8 + c2 + 1] = a1;
    g_xh[n * 4 + c] = pack_h8(a0, a1);   // gather source for next conv
}

// ---------------------------------------------------------------- output head

__global__ void __launch_bounds__(256) k_final(const float4* __restrict__ H,
                                               const float* __restrict__ W1,
                                               const float* __restrict__ b1,
                                               float* __restrict__ out) {
    int tid = blockIdx.x * 256 + threadIdx.x;
    int n = tid >> 2, c = tid & 3;
    if (n >= NN) return;
    int c2 = c * 2;
    float4 h0 = __ldg(&H[n * 8 + c2]);
    float4 h1 = __ldg(&H[n * 8 + c2 + 1]);
    float4 w0 = __ldg(&((const float4*)W1)[c2]);
    float4 w1 = __ldg(&((const float4*)W1)[c2 + 1]);
    float v = h0.x * w0.x + h0.y * w0.y + h0.z * w0.z + h0.w * w0.w
            + h1.x * w1.x + h1.y * w1.y + h1.z * w1.z + h1.w * w1.w;
    v += __shfl_down_sync(0xffffffffu, v, 2, 4);
    v += __shfl_down_sync(0xffffffffu, v, 1, 4);
    if (c == 0) out[n] = v + __ldg(b1);
}

// ---------------------------------------------------------------- launch

extern "C" void kernel_launch(void* const* d_in, const int* in_sizes, int n_in,
                              void* d_out, int out_size) {
    // ---- resolve inputs by element count (robust to metadata ordering) ----
    int idx_x = 0, idx_ei = 1, idx_W0 = 2, idx_b1 = 13;
    int chebW[4] = {4, 6, 8, 10};
    int chebB[4] = {5, 7, 9, 11};
    int idx_b0 = 3, idx_W1 = 12;
    {
        int cw[4], ncw = 0, s32[8], ns = 0;
        int ix = -1, iei = -1, iw0 = -1, ib1 = -1;
        for (int i = 0; i < n_in; i++) {
            int s = in_sizes[i];
            if (s == 600000) ix = i;
            else if (s == 6400000) iei = i;
            else if (s == 96) iw0 = i;
            else if (s == 1) ib1 = i;
            else if (s == 3072 && ncw < 4) cw[ncw++] = i;
            else if (s == 32 && ns < 8) s32[ns++] = i;
        }
        if (ix >= 0 && iei >= 0 && iw0 >= 0 && ib1 >= 0 && ncw == 4 && ns == 6) {
            idx_x = ix; idx_ei = iei; idx_W0 = iw0; idx_b1 = ib1;
            int rem[2], nr = 0;
            for (int k = 0; k < 4; k++) chebW[k] = cw[k];
            for (int i = 0; i < 6; i++) {
                int isb = 0;
                for (int k = 0; k < 4; k++)
                    if (s32[i] == cw[k] + 1) { chebB[k] = s32[i]; isb = 1; }
                if (!isb && nr < 2) rem[nr++] = s32[i];
            }
            if (nr == 2) {
                if (rem[1] == rem[0] + 1) { idx_W1 = rem[0]; idx_b0 = rem[1]; }
                else                      { idx_b0 = rem[0]; idx_W1 = rem[1]; }
            }
        }
    }

    const float* x    = (const float*)d_in[idx_x];
    const void*  ei   = d_in[idx_ei];
    const float* W0   = (const float*)d_in[idx_W0];
    const float* b0   = (const float*)d_in[idx_b0];
    const float* cW[4], *cB[4];
    for (int k = 0; k < 4; k++) { cW[k] = (const float*)d_in[chebW[k]]; cB[k] = (const float*)d_in[chebB[k]]; }
    const float* W1   = (const float*)d_in[idx_W1];
    const float* b1   = (const float*)d_in[idx_b1];
    float*       out  = (float*)d_out;

    float4 *ph, *pa, *pt1;
    cudaGetSymbolAddress((void**)&ph,  g_h);
    cudaGetSymbolAddress((void**)&pa,  g_a);
    cudaGetSymbolAddress((void**)&pt1, g_t1);

    const int NB_N = (NN + 255) / 256;
    const int NB_E = (EE + 255) / 256;
    const int NB_4 = (NN * 4 + 255) / 256;   // 3125 blocks: 4 threads per node

    k_detect<<<1, 1>>>(ei);
    k_zero<<<NB_N, 256>>>();
    k_count<<<NB_E, 256>>>(ei);
    k_dinv_rowalloc<<<NB_N, 256>>>();
    k_fill<<<NB_E, 256>>>(ei);
    k_input<<<NB_4, 256>>>(x, W0, b0);

    auto cheb = [&](int k, const float4* Xb, const float4* resb, float4* outb) {
        k_prop_csr<<<NB_4, 256>>>(pt1);
        k_prop_combine<<<NB_4, 256>>>(Xb, pt1, cW[k], cB[k], resb, outb, 1);
    };

    // block 1: h0=h; h=relu(conv11(h)); h=relu(conv12(h)+h0)
    cheb(0, ph, nullptr, pa);
    cheb(1, pa, ph,      ph);
    // block 2
    cheb(2, ph, nullptr, pa);
    cheb(3, pa, ph,      ph);

    k_final<<<NB_4, 256>>>(ph, W1, b1, out);
}